// round 12
// baseline (speedup 1.0000x reference)
#include <cuda_runtime.h>
#include <cstdint>

// ---------------------------------------------------------------------------
// MSC_Cell: B=128, S=4096, STATE_DIM=5, HIDDEN=32, D_IN=9
// Kernel 1: per-batch-row prefix scan of delta_x[...,2] (+ init temp)
// Kernel 2: gated-tanh MLP, 2 tokens/thread, f32x2 packed FMAs,
//           tanh.approx.f32, 8-neuron chunking + epilogue reload to cut
//           register liveness -> 3 CTAs/SM (was 2).
// ---------------------------------------------------------------------------

#define BB 128
#define SS 4096

__device__ float g_temp[BB * SS];

typedef unsigned long long ull;

// ---- f32x2 helpers ----
__device__ __forceinline__ ull pk2(float x) {
    ull r;
    asm("mov.b64 %0, {%1, %1};" : "=l"(r) : "f"(x));
    return r;
}
__device__ __forceinline__ ull f2fma(ull a, ull b, ull c) {
    ull d;
    asm("fma.rn.f32x2 %0, %1, %2, %3;" : "=l"(d) : "l"(a), "l"(b), "l"(c));
    return d;
}
__device__ __forceinline__ void unpk(ull v, float& lo, float& hi) {
    asm("mov.b64 {%0, %1}, %2;" : "=f"(lo), "=f"(hi) : "l"(v));
}
__device__ __forceinline__ float tanh_ap(float x) {
    float y;
    asm("tanh.approx.f32 %0, %1;" : "=f"(y) : "f"(x));
    return y;
}

// ---------------------------------------------------------------------------
// Kernel 1: prefix scan. One block per batch row, 512 threads x 8 elements.
// ---------------------------------------------------------------------------
__global__ void scan_kernel(const float* __restrict__ dx) {
    int b = blockIdx.x;
    const float* base = dx + (size_t)b * SS * 6;
    int t = threadIdx.x;  // 0..511

    float v[8];
    float run = 0.0f;
#pragma unroll
    for (int j = 0; j < 8; j++) {
        run += base[(t * 8 + j) * 6 + 2];
        v[j] = run;
    }

    float incl = run;
    int lane = t & 31, wid = t >> 5;
#pragma unroll
    for (int o = 1; o < 32; o <<= 1) {
        float n = __shfl_up_sync(0xffffffffu, incl, o);
        if (lane >= o) incl += n;
    }
    __shared__ float wsum[16];
    if (lane == 31) wsum[wid] = incl;
    __syncthreads();
    float woff = 0.0f;
    for (int k = 0; k < wid; k++) woff += wsum[k];

    float excl = woff + incl - run;
    float init = base[5];

    float* o = g_temp + (size_t)b * SS + t * 8;
#pragma unroll
    for (int j = 0; j < 8; j++) o[j] = excl + v[j] + init;
}

// ---------------------------------------------------------------------------
// SMEM layout (floats)
// ---------------------------------------------------------------------------
enum {
    A0_OFF = 0,      // Wa0: 9x32
    B0_OFF = 288,    // Wb0: 9x32
    A1_OFF = 576,    // Wa1: 32x32
    B1_OFF = 1600,   // Wb1: 32x32
    HD_OFF = 2624,   // head matrix 32x8: [alpha,beta,gamma,c0..c4]
    BA0_OFF = 2880,
    BB0_OFF = 2912,
    BA1_OFF = 2944,
    BB1_OFF = 2976,
    HB_OFF  = 3008,  // 8 head biases
    WO_OFF  = 3016,  // W_out: 5
    SW_TOTAL = 3040
};

// ---------------------------------------------------------------------------
// One gated layer for TWO tokens, processed in four 8-neuron chunks.
// Each weight LDS feeds FMAs for both tokens; chunking bounds the live
// accumulator set to 16 x 64-bit.
// ---------------------------------------------------------------------------
template <int NIN>
__device__ __forceinline__ void mlp2(const float* __restrict__ x0v,
                                     const float* __restrict__ x1v,
                                     const float* sA, const float* sB,
                                     const float* sBa, const float* sBb,
                                     float* __restrict__ o0,
                                     float* __restrict__ o1) {
#pragma unroll
    for (int c = 0; c < 4; c++) {
        ull aA0[4], aA1[4], aB0[4], aB1[4];
#pragma unroll
        for (int p = 0; p < 4; p++) {
            ull vA = *(const ull*)(sBa + c * 8 + 2 * p);
            ull vB = *(const ull*)(sBb + c * 8 + 2 * p);
            aA0[p] = vA; aA1[p] = vA;
            aB0[p] = vB; aB1[p] = vB;
        }
#pragma unroll
        for (int i = 0; i < NIN; i++) {
            ull x0 = pk2(x0v[i]);
            ull x1 = pk2(x1v[i]);
            const float* wa = sA + i * 32 + c * 8;
            const float* wb = sB + i * 32 + c * 8;
            ulonglong2 wa01 = *(const ulonglong2*)(wa);
            ulonglong2 wa23 = *(const ulonglong2*)(wa + 4);
            ulonglong2 wb01 = *(const ulonglong2*)(wb);
            ulonglong2 wb23 = *(const ulonglong2*)(wb + 4);

            aA0[0] = f2fma(x0, wa01.x, aA0[0]);  aA1[0] = f2fma(x1, wa01.x, aA1[0]);
            aA0[1] = f2fma(x0, wa01.y, aA0[1]);  aA1[1] = f2fma(x1, wa01.y, aA1[1]);
            aA0[2] = f2fma(x0, wa23.x, aA0[2]);  aA1[2] = f2fma(x1, wa23.x, aA1[2]);
            aA0[3] = f2fma(x0, wa23.y, aA0[3]);  aA1[3] = f2fma(x1, wa23.y, aA1[3]);

            aB0[0] = f2fma(x0, wb01.x, aB0[0]);  aB1[0] = f2fma(x1, wb01.x, aB1[0]);
            aB0[1] = f2fma(x0, wb01.y, aB0[1]);  aB1[1] = f2fma(x1, wb01.y, aB1[1]);
            aB0[2] = f2fma(x0, wb23.x, aB0[2]);  aB1[2] = f2fma(x1, wb23.x, aB1[2]);
            aB0[3] = f2fma(x0, wb23.y, aB0[3]);  aB1[3] = f2fma(x1, wb23.y, aB1[3]);
        }
#pragma unroll
        for (int p = 0; p < 4; p++) {
            float a0, a1, b0, b1;
            unpk(aA0[p], a0, a1);
            unpk(aB0[p], b0, b1);
            o0[c * 8 + 2 * p]     = tanh_ap(a0) * tanh_ap(b0);
            o0[c * 8 + 2 * p + 1] = tanh_ap(a1) * tanh_ap(b1);
            unpk(aA1[p], a0, a1);
            unpk(aB1[p], b0, b1);
            o1[c * 8 + 2 * p]     = tanh_ap(a0) * tanh_ap(b0);
            o1[c * 8 + 2 * p + 1] = tanh_ap(a1) * tanh_ap(b1);
        }
    }
}

// Per-token epilogue after the head GEMV. Reloads h/d from global (L1-hot)
// instead of keeping them live across the MLP (saves ~16 registers).
__device__ __forceinline__ void finish_token(
    float aP, float bP, float gP,
    float c0P, float c1P, float c2P, float c3P, float c4P,
    const float* __restrict__ h_prev, const float* __restrict__ dx,
    const float* sWO, float* __restrict__ out, int token, int ntok) {
    const float* hp = h_prev + (size_t)token * 5;
    const float* dp = dx + (size_t)token * 6;
    float h0 = hp[0], h1 = hp[1], h2 = hp[2], h3 = hp[3], h4 = hp[4];
    float d0 = dp[0], d1 = dp[1], d2 = dp[2];

    float alpha = __expf(aP);
    float beta  = __expf(bP);
    float gamma = __expf(gP);
    float c0 = tanh_ap(c0P), c1 = tanh_ap(c1P), c2 = tanh_ap(c2P);
    float c3 = tanh_ap(c3P), c4 = tanh_ap(c4P);

    float zarg = fmaf(alpha, fabsf(d0), fmaf(beta, d1, gamma * fabsf(d2)));
    float z = 1.0f - __expf(-zarg);

    float n0 = fmaf(z, c0 - h0, h0);
    float n1 = fmaf(z, c1 - h1, h1);
    float n2 = fmaf(z, c2 - h2, h2);
    float n3 = fmaf(z, c3 - h3, h3);
    float n4 = fmaf(z, c4 - h4, h4);

    float sigma = n0 * sWO[0];
    sigma = fmaf(n1, sWO[1], sigma);
    sigma = fmaf(n2, sWO[2], sigma);
    sigma = fmaf(n3, sWO[3], sigma);
    sigma = fmaf(n4, sWO[4], sigma);

    float* oh = out + (size_t)token * 5;
    oh[0] = n0; oh[1] = n1; oh[2] = n2; oh[3] = n3; oh[4] = n4;
    out[(size_t)ntok * 5 + token] = sigma;
}

// ---------------------------------------------------------------------------
// Kernel 2: 128 threads/block, 2 tokens per thread (t and t+128), 3 CTAs/SM.
// ---------------------------------------------------------------------------
__global__ __launch_bounds__(128, 3) void msc_main(
    const float* __restrict__ h_prev, const float* __restrict__ dx,
    const float* __restrict__ Wa0, const float* __restrict__ ba0,
    const float* __restrict__ Wb0, const float* __restrict__ bb0,
    const float* __restrict__ Wa1, const float* __restrict__ ba1,
    const float* __restrict__ Wb1, const float* __restrict__ bb1,
    const float* __restrict__ W_alpha, const float* __restrict__ b_alpha,
    const float* __restrict__ W_beta,  const float* __restrict__ b_beta,
    const float* __restrict__ W_gamma, const float* __restrict__ b_gamma,
    const float* __restrict__ W_c,     const float* __restrict__ b_c,
    const float* __restrict__ W_out,
    float* __restrict__ out, int ntok) {
    __shared__ __align__(16) float sW[SW_TOTAL];
    int tid = threadIdx.x;

    // cooperative weight staging (128 threads)
    for (int i = tid; i < 288; i += 128) {
        sW[A0_OFF + i] = Wa0[i];
        sW[B0_OFF + i] = Wb0[i];
    }
    for (int i = tid; i < 1024; i += 128) {
        sW[A1_OFF + i] = Wa1[i];
        sW[B1_OFF + i] = Wb1[i];
    }
    for (int idx = tid; idx < 256; idx += 128) {
        int i = idx >> 3, j = idx & 7;  // head matrix row i: [alpha,beta,gamma,c0..c4]
        float v;
        if (j == 0)      v = W_alpha[i];
        else if (j == 1) v = W_beta[i];
        else if (j == 2) v = W_gamma[i];
        else             v = W_c[i * 5 + (j - 3)];
        sW[HD_OFF + idx] = v;
    }
    if (tid < 32) {
        sW[BA0_OFF + tid] = ba0[tid];
        sW[BB0_OFF + tid] = bb0[tid];
        sW[BA1_OFF + tid] = ba1[tid];
        sW[BB1_OFF + tid] = bb1[tid];
    }
    if (tid < 8) {
        float v;
        if (tid == 0)      v = b_alpha[0];
        else if (tid == 1) v = b_beta[0];
        else if (tid == 2) v = b_gamma[0];
        else               v = b_c[tid - 3];
        sW[HB_OFF + tid] = v;
    }
    if (tid < 5) sW[WO_OFF + tid] = W_out[tid];
    __syncthreads();

    int t0 = blockIdx.x * 256 + tid;
    int t1 = t0 + 128;
    if (t1 >= ntok) {  // exact grids never take this, kept for safety
        if (t0 >= ntok) return;
        t1 = t0;
    }

    // -------- per-token input prep (front-batched global loads) --------
    float lin0[9], lin1[9];
    {
        const float* hp0 = h_prev + (size_t)t0 * 5;
        const float* dp0 = dx + (size_t)t0 * 6;
        float d0 = dp0[0], d1 = dp0[1], d2 = dp0[2];
        float ss  = fmaf(d0, d0, fmaf(d1, d1, d2 * d2));
        float inv = __fdividef(1.0f, fmaxf(sqrtf(ss), 1e-7f));
        lin0[0] = hp0[0]; lin0[1] = hp0[1]; lin0[2] = hp0[2];
        lin0[3] = hp0[3]; lin0[4] = hp0[4];
        lin0[5] = g_temp[t0];
        lin0[6] = d0 * inv; lin0[7] = d1 * inv; lin0[8] = d2 * inv;
    }
    {
        const float* hp1 = h_prev + (size_t)t1 * 5;
        const float* dp1 = dx + (size_t)t1 * 6;
        float d0 = dp1[0], d1 = dp1[1], d2 = dp1[2];
        float ss  = fmaf(d0, d0, fmaf(d1, d1, d2 * d2));
        float inv = __fdividef(1.0f, fmaxf(sqrtf(ss), 1e-7f));
        lin1[0] = hp1[0]; lin1[1] = hp1[1]; lin1[2] = hp1[2];
        lin1[3] = hp1[3]; lin1[4] = hp1[4];
        lin1[5] = g_temp[t1];
        lin1[6] = d0 * inv; lin1[7] = d1 * inv; lin1[8] = d2 * inv;
    }

    float l1a[32], l1b[32];
    mlp2<9>(lin0, lin1, sW + A0_OFF, sW + B0_OFF, sW + BA0_OFF, sW + BB0_OFF,
            l1a, l1b);
    float l2a[32], l2b[32];
    mlp2<32>(l1a, l1b, sW + A1_OFF, sW + B1_OFF, sW + BA1_OFF, sW + BB1_OFF,
             l2a, l2b);

    // -------- heads: 32x8 GEMV for both tokens --------
    ull aH0[4], aH1[4];
#pragma unroll
    for (int p = 0; p < 4; p++) {
        ull v = *(const ull*)(sW + HB_OFF + 2 * p);
        aH0[p] = v; aH1[p] = v;
    }
#pragma unroll
    for (int i = 0; i < 32; i++) {
        ull x0 = pk2(l2a[i]);
        ull x1 = pk2(l2b[i]);
        const float* wh = sW + HD_OFF + i * 8;
        ulonglong2 w01 = *(const ulonglong2*)(wh);
        ulonglong2 w23 = *(const ulonglong2*)(wh + 4);
        aH0[0] = f2fma(x0, w01.x, aH0[0]);  aH1[0] = f2fma(x1, w01.x, aH1[0]);
        aH0[1] = f2fma(x0, w01.y, aH0[1]);  aH1[1] = f2fma(x1, w01.y, aH1[1]);
        aH0[2] = f2fma(x0, w23.x, aH0[2]);  aH1[2] = f2fma(x1, w23.x, aH1[2]);
        aH0[3] = f2fma(x0, w23.y, aH0[3]);  aH1[3] = f2fma(x1, w23.y, aH1[3]);
    }

    {
        float aP, bP, gP, c0P, c1P, c2P, c3P, c4P;
        unpk(aH0[0], aP, bP);
        unpk(aH0[1], gP, c0P);
        unpk(aH0[2], c1P, c2P);
        unpk(aH0[3], c3P, c4P);
        finish_token(aP, bP, gP, c0P, c1P, c2P, c3P, c4P,
                     h_prev, dx, sW + WO_OFF, out, t0, ntok);
    }
    {
        float aP, bP, gP, c0P, c1P, c2P, c3P, c4P;
        unpk(aH1[0], aP, bP);
        unpk(aH1[1], gP, c0P);
        unpk(aH1[2], c1P, c2P);
        unpk(aH1[3], c3P, c4P);
        finish_token(aP, bP, gP, c0P, c1P, c2P, c3P, c4P,
                     h_prev, dx, sW + WO_OFF, out, t1, ntok);
    }
}

// ---------------------------------------------------------------------------
extern "C" void kernel_launch(void* const* d_in, const int* in_sizes, int n_in,
                              void* d_out, int out_size) {
    const float* h_prev  = (const float*)d_in[0];
    const float* dx      = (const float*)d_in[1];
    const float* Wa0     = (const float*)d_in[2];
    const float* ba0     = (const float*)d_in[3];
    const float* Wb0     = (const float*)d_in[4];
    const float* bb0     = (const float*)d_in[5];
    const float* Wa1     = (const float*)d_in[6];
    const float* ba1     = (const float*)d_in[7];
    const float* Wb1     = (const float*)d_in[8];
    const float* bb1     = (const float*)d_in[9];
    const float* W_alpha = (const float*)d_in[10];
    const float* b_alpha = (const float*)d_in[11];
    const float* W_beta  = (const float*)d_in[12];
    const float* b_beta  = (const float*)d_in[13];
    const float* W_gamma = (const float*)d_in[14];
    const float* b_gamma = (const float*)d_in[15];
    const float* W_c     = (const float*)d_in[16];
    const float* b_c     = (const float*)d_in[17];
    const float* W_out   = (const float*)d_in[18];
    float* out = (float*)d_out;

    int ntok = in_sizes[0] / 5;   // B*S
    int batches = ntok / SS;      // B

    scan_kernel<<<batches, 512>>>(dx);

    int blocks = (ntok + 255) / 256;  // 256 tokens per block (128 thr x 2)
    msc_main<<<blocks, 128>>>(h_prev, dx,
                              Wa0, ba0, Wb0, bb0, Wa1, ba1, Wb1, bb1,
                              W_alpha, b_alpha, W_beta, b_beta,
                              W_gamma, b_gamma, W_c, b_c, W_out,
                              out, ntok);
}

// round 14
// speedup vs baseline: 2.2776x; 2.2776x over previous
#include <cuda_runtime.h>
#include <cuda_fp16.h>
#include <cstdint>

// ---------------------------------------------------------------------------
// MSC_Cell via warp-level HMMA (mma.sync m16n8k16 f16->f32), sm_103-safe.
//   Tile = 128 tokens per block iteration, each of 4 warps owns 32 tokens.
//   L0: A[32x16] @ W1^T[16x64] -> acc (bias in f32 init)   16 mma/warp
//   L1: A[32x32] @ W2^T[32x64] -> acc (2 k-steps)          32 mma/warp
//   heads: A[32x32] @ Wh^T[32x8]                            4 mma/warp
//   Gating tanh(A)*tanh(B) is thread-local in the C fragment.
//   Weights live in smem; B-fragments loaded once, resident in registers.
// ---------------------------------------------------------------------------

#define BB 128
#define SS 4096
#define NTILE ((BB * SS) / 128)
#define GRID_MAIN 444          // 3 CTAs/SM x 148 SMs, persistent
#define HS 24                  // halves per smem row (48B stride -> LDSM conflict-free)

__device__ float g_temp[BB * SS];

// ---- helpers ----
__device__ __forceinline__ uint32_t smem_u32(const void* p) {
    uint32_t a;
    asm("{ .reg .u64 t; cvta.to.shared.u64 t, %1; cvt.u32.u64 %0, t; }"
        : "=r"(a) : "l"(p));
    return a;
}
__device__ __forceinline__ float tanh_ap(float x) {
    float y;
    asm("tanh.approx.f32 %0, %1;" : "=f"(y) : "f"(x));
    return y;
}
__device__ __forceinline__ uint32_t h2u(float a, float b) {
    __half2 h = __floats2half2_rn(a, b);
    return *reinterpret_cast<uint32_t*>(&h);
}
__device__ __forceinline__ void sts32(uint32_t addr, uint32_t v) {
    asm volatile("st.shared.b32 [%0], %1;" :: "r"(addr), "r"(v) : "memory");
}
__device__ __forceinline__ void ldsm_x4(uint32_t* r, uint32_t addr) {
    asm volatile("ldmatrix.sync.aligned.m8n8.x4.shared.b16 {%0,%1,%2,%3}, [%4];"
                 : "=r"(r[0]), "=r"(r[1]), "=r"(r[2]), "=r"(r[3]) : "r"(addr));
}
__device__ __forceinline__ void ldsm_x2(uint32_t* r, uint32_t addr) {
    asm volatile("ldmatrix.sync.aligned.m8n8.x2.shared.b16 {%0,%1}, [%2];"
                 : "=r"(r[0]), "=r"(r[1]) : "r"(addr));
}
__device__ __forceinline__ void mma16816(float* c, const uint32_t* a,
                                         const uint32_t* b) {
    asm volatile(
        "mma.sync.aligned.m16n8k16.row.col.f32.f16.f16.f32 "
        "{%0,%1,%2,%3}, {%4,%5,%6,%7}, {%8,%9}, {%0,%1,%2,%3};"
        : "+f"(c[0]), "+f"(c[1]), "+f"(c[2]), "+f"(c[3])
        : "r"(a[0]), "r"(a[1]), "r"(a[2]), "r"(a[3]), "r"(b[0]), "r"(b[1]));
}

// ---------------------------------------------------------------------------
// Kernel 1: prefix scan (unchanged, proven).
// ---------------------------------------------------------------------------
__global__ void scan_kernel(const float* __restrict__ dx) {
    int b = blockIdx.x;
    const float* base = dx + (size_t)b * SS * 6;
    int t = threadIdx.x;  // 0..511

    float v[8];
    float run = 0.0f;
#pragma unroll
    for (int j = 0; j < 8; j++) {
        run += base[(t * 8 + j) * 6 + 2];
        v[j] = run;
    }
    float incl = run;
    int lane = t & 31, wid = t >> 5;
#pragma unroll
    for (int o = 1; o < 32; o <<= 1) {
        float n = __shfl_up_sync(0xffffffffu, incl, o);
        if (lane >= o) incl += n;
    }
    __shared__ float wsum[16];
    if (lane == 31) wsum[wid] = incl;
    __syncthreads();
    float woff = 0.0f;
    for (int k = 0; k < wid; k++) woff += wsum[k];
    float excl = woff + incl - run;
    float init = base[5];
    float* o = g_temp + (size_t)b * SS + t * 8;
#pragma unroll
    for (int j = 0; j < 8; j++) o[j] = excl + v[j] + init;
}

// ---------------------------------------------------------------------------
// Kernel 2: HMMA main, persistent. 128 threads = 4 warps x 32 tokens/tile.
// ---------------------------------------------------------------------------
__global__ __launch_bounds__(128) void msc_hmma(
    const float* __restrict__ h_prev, const float* __restrict__ dx,
    const float* __restrict__ Wa0, const float* __restrict__ ba0,
    const float* __restrict__ Wb0, const float* __restrict__ bb0,
    const float* __restrict__ Wa1, const float* __restrict__ ba1,
    const float* __restrict__ Wb1, const float* __restrict__ bb1,
    const float* __restrict__ W_alpha, const float* __restrict__ b_alpha,
    const float* __restrict__ W_beta,  const float* __restrict__ b_beta,
    const float* __restrict__ W_gamma, const float* __restrict__ b_gamma,
    const float* __restrict__ W_c,     const float* __restrict__ b_c,
    const float* __restrict__ W_out,
    float* __restrict__ out, int ntok) {
    __shared__ __align__(16) __half sAct[2][128 * HS];   // chunk0 doubles as input
    __shared__ __align__(16) __half sW1[64 * HS];        // L0 weights, k 0..15
    __shared__ __align__(16) __half sW2[2][64 * HS];     // L1 weights, 2 k-chunks
    __shared__ __align__(16) __half sWh[2][8 * HS];      // head weights, 2 k-chunks
    __shared__ __align__(16) float sB0[64];
    __shared__ __align__(16) float sB1v[64];
    __shared__ __align__(16) float sBH[8];
    __shared__ __align__(16) float sWO[8];
    __shared__ __align__(16) float sHC[128 * 12];        // head C, stride 12 floats

    int tid = threadIdx.x;
    int lane = tid & 31;
    int wid = tid >> 5;

    // ---------------- one-time weight staging ----------------
    for (int i = tid; i < 64 * HS; i += 128) sW1[i] = __float2half(0.0f);
    __syncthreads();
    for (int idx = tid; idx < 64 * 9; idx += 128) {
        int n = idx / 9, k = idx % 9;
        float w = (n < 32) ? Wa0[k * 32 + n] : Wb0[k * 32 + (n - 32)];
        sW1[n * HS + k] = __float2half(w);
    }
    for (int idx = tid; idx < 64 * 32; idx += 128) {
        int n = idx / 32, k = idx % 32;
        float w = (n < 32) ? Wa1[k * 32 + n] : Wb1[k * 32 + (n - 32)];
        sW2[k >> 4][n * HS + (k & 15)] = __float2half(w);
    }
    for (int idx = tid; idx < 8 * 32; idx += 128) {
        int j = idx / 32, k = idx % 32;
        float w;
        if (j == 0)      w = W_alpha[k];
        else if (j == 1) w = W_beta[k];
        else if (j == 2) w = W_gamma[k];
        else             w = W_c[k * 5 + (j - 3)];
        sWh[k >> 4][j * HS + (k & 15)] = __float2half(w);
    }
    if (tid < 64) {
        sB0[tid]  = (tid < 32) ? ba0[tid] : bb0[tid - 32];
        sB1v[tid] = (tid < 32) ? ba1[tid] : bb1[tid - 32];
    }
    if (tid < 8) {
        float v;
        if (tid == 0)      v = b_alpha[0];
        else if (tid == 1) v = b_beta[0];
        else if (tid == 2) v = b_gamma[0];
        else               v = b_c[tid - 3];
        sBH[tid] = v;
        sWO[tid] = (tid < 5) ? W_out[tid] : 0.0f;
    }
    __syncthreads();

    uint32_t uAct0 = smem_u32(&sAct[0][0]);
    uint32_t uAct1 = smem_u32(&sAct[1][0]);

    // ---------------- resident B fragments ----------------
    int bl = lane & 15;
    int brow = bl & 7;
    int bko = (bl >> 3) * 16;

    uint32_t w1f[8][2], w2f[2][8][2], whf[2][2];
    {
        uint32_t uW1 = smem_u32(sW1);
#pragma unroll
        for (int nt = 0; nt < 8; nt++)
            ldsm_x2(w1f[nt], uW1 + (nt * 8 + brow) * (HS * 2) + bko);
#pragma unroll
        for (int c = 0; c < 2; c++) {
            uint32_t uW2 = smem_u32(&sW2[c][0]);
#pragma unroll
            for (int nt = 0; nt < 8; nt++)
                ldsm_x2(w2f[c][nt], uW2 + (nt * 8 + brow) * (HS * 2) + bko);
        }
#pragma unroll
        for (int c = 0; c < 2; c++)
            ldsm_x2(whf[c], smem_u32(&sWh[c][0]) + brow * (HS * 2) + bko);
    }

    int ai = lane & 7;
    int asel = lane >> 3;
    int arow_off = (asel & 1) * 8 + ai;
    int abyte_off = (asel >> 1) * 16;

    int r0w = wid * 32;
    int lq = lane >> 2;
    int lr = lane & 3;

    // ---------------- persistent tile loop ----------------
    for (int tile = blockIdx.x; tile < NTILE; tile += GRID_MAIN) {
        int token = tile * 128 + r0w + lane;

        const float* hp = h_prev + (size_t)token * 5;
        const float* dp = dx + (size_t)token * 6;
        float h0 = hp[0], h1 = hp[1], h2 = hp[2], h3 = hp[3], h4 = hp[4];
        float d0 = dp[0], d1 = dp[1], d2 = dp[2];
        float temp = g_temp[token];
        float ssn = fmaf(d0, d0, fmaf(d1, d1, d2 * d2));
        float inv = __fdividef(1.0f, fmaxf(sqrtf(ssn), 1e-7f));

        {
            __half* rowp = &sAct[0][(r0w + lane) * HS];
            uint4 b0 = make_uint4(h2u(h0, h1), h2u(h2, h3), h2u(h4, temp),
                                  h2u(d0 * inv, d1 * inv));
            uint4 b1 = make_uint4(h2u(d2 * inv, 0.0f), 0, 0, 0);
            *(uint4*)rowp = b0;
            *(uint4*)(rowp + 8) = b1;
        }
        __syncwarp();

        float acc[2][8][4];
#pragma unroll
        for (int nt = 0; nt < 8; nt++) {
            float2 bv = *(const float2*)&sB0[nt * 8 + 2 * lr];
            acc[0][nt][0] = bv.x; acc[0][nt][1] = bv.y;
            acc[0][nt][2] = bv.x; acc[0][nt][3] = bv.y;
            acc[1][nt][0] = bv.x; acc[1][nt][1] = bv.y;
            acc[1][nt][2] = bv.x; acc[1][nt][3] = bv.y;
        }
#pragma unroll
        for (int m = 0; m < 2; m++) {
            uint32_t a[4];
            ldsm_x4(a, uAct0 + (r0w + m * 16 + arow_off) * (HS * 2) + abyte_off);
#pragma unroll
            for (int nt = 0; nt < 8; nt++) mma16816(acc[m][nt], a, w1f[nt]);
        }
        __syncwarp();

#pragma unroll
        for (int m = 0; m < 2; m++) {
#pragma unroll
            for (int nt = 0; nt < 4; nt++) {
                float g0 = tanh_ap(acc[m][nt][0]) * tanh_ap(acc[m][nt + 4][0]);
                float g1 = tanh_ap(acc[m][nt][1]) * tanh_ap(acc[m][nt + 4][1]);
                float g2 = tanh_ap(acc[m][nt][2]) * tanh_ap(acc[m][nt + 4][2]);
                float g3 = tanh_ap(acc[m][nt][3]) * tanh_ap(acc[m][nt + 4][3]);
                int colb = ((nt & 1) * 8 + 2 * lr) * 2;
                uint32_t base = (nt < 2) ? uAct0 : uAct1;
                int row = r0w + m * 16 + lq;
                sts32(base + row * (HS * 2) + colb, h2u(g0, g1));
                sts32(base + (row + 8) * (HS * 2) + colb, h2u(g2, g3));
            }
        }
        __syncwarp();

#pragma unroll
        for (int nt = 0; nt < 8; nt++) {
            float2 bv = *(const float2*)&sB1v[nt * 8 + 2 * lr];
            acc[0][nt][0] = bv.x; acc[0][nt][1] = bv.y;
            acc[0][nt][2] = bv.x; acc[0][nt][3] = bv.y;
            acc[1][nt][0] = bv.x; acc[1][nt][1] = bv.y;
            acc[1][nt][2] = bv.x; acc[1][nt][3] = bv.y;
        }
#pragma unroll
        for (int c = 0; c < 2; c++) {
            uint32_t base = (c == 0) ? uAct0 : uAct1;
#pragma unroll
            for (int m = 0; m < 2; m++) {
                uint32_t a[4];
                ldsm_x4(a, base + (r0w + m * 16 + arow_off) * (HS * 2) + abyte_off);
#pragma unroll
                for (int nt = 0; nt < 8; nt++) mma16816(acc[m][nt], a, w2f[c][nt]);
            }
        }
        __syncwarp();

#pragma unroll
        for (int m = 0; m < 2; m++) {
#pragma unroll
            for (int nt = 0; nt < 4; nt++) {
                float g0 = tanh_ap(acc[m][nt][0]) * tanh_ap(acc[m][nt + 4][0]);
                float g1 = tanh_ap(acc[m][nt][1]) * tanh_ap(acc[m][nt + 4][1]);
                float g2 = tanh_ap(acc[m][nt][2]) * tanh_ap(acc[m][nt + 4][2]);
                float g3 = tanh_ap(acc[m][nt][3]) * tanh_ap(acc[m][nt + 4][3]);
                int colb = ((nt & 1) * 8 + 2 * lr) * 2;
                uint32_t base = (nt < 2) ? uAct0 : uAct1;
                int row = r0w + m * 16 + lq;
                sts32(base + row * (HS * 2) + colb, h2u(g0, g1));
                sts32(base + (row + 8) * (HS * 2) + colb, h2u(g2, g3));
            }
        }
        __syncwarp();

        float hacc[2][4];
        {
            float2 bv = *(const float2*)&sBH[2 * lr];
            hacc[0][0] = bv.x; hacc[0][1] = bv.y; hacc[0][2] = bv.x; hacc[0][3] = bv.y;
            hacc[1][0] = bv.x; hacc[1][1] = bv.y; hacc[1][2] = bv.x; hacc[1][3] = bv.y;
        }
#pragma unroll
        for (int c = 0; c < 2; c++) {
            uint32_t base = (c == 0) ? uAct0 : uAct1;
#pragma unroll
            for (int m = 0; m < 2; m++) {
                uint32_t a[4];
                ldsm_x4(a, base + (r0w + m * 16 + arow_off) * (HS * 2) + abyte_off);
                mma16816(hacc[m], a, whf[c]);
            }
        }
#pragma unroll
        for (int m = 0; m < 2; m++) {
            int row = r0w + m * 16 + lq;
            *(float2*)&sHC[row * 12 + 2 * lr] = make_float2(hacc[m][0], hacc[m][1]);
            *(float2*)&sHC[(row + 8) * 12 + 2 * lr] = make_float2(hacc[m][2], hacc[m][3]);
        }
        __syncwarp();

        {
            int tr = r0w + lane;
            float4 q0 = *(const float4*)&sHC[tr * 12];
            float4 q1 = *(const float4*)&sHC[tr * 12 + 4];
            float alpha = __expf(q0.x);
            float beta  = __expf(q0.y);
            float gamma = __expf(q0.z);
            float c0 = tanh_ap(q0.w), c1 = tanh_ap(q1.x), c2 = tanh_ap(q1.y);
            float c3 = tanh_ap(q1.z), c4 = tanh_ap(q1.w);

            float zarg = fmaf(alpha, fabsf(d0), fmaf(beta, d1, gamma * fabsf(d2)));
            float z = 1.0f - __expf(-zarg);

            float n0 = fmaf(z, c0 - h0, h0);
            float n1 = fmaf(z, c1 - h1, h1);
            float n2 = fmaf(z, c2 - h2, h2);
            float n3 = fmaf(z, c3 - h3, h3);
            float n4 = fmaf(z, c4 - h4, h4);

            float sigma = n0 * sWO[0];
            sigma = fmaf(n1, sWO[1], sigma);
            sigma = fmaf(n2, sWO[2], sigma);
            sigma = fmaf(n3, sWO[3], sigma);
            sigma = fmaf(n4, sWO[4], sigma);

            float* oh = out + (size_t)token * 5;
            oh[0] = n0; oh[1] = n1; oh[2] = n2; oh[3] = n3; oh[4] = n4;
            out[(size_t)ntok * 5 + token] = sigma;
        }
        __syncwarp();
    }
}

// ---------------------------------------------------------------------------
extern "C" void kernel_launch(void* const* d_in, const int* in_sizes, int n_in,
                              void* d_out, int out_size) {
    const float* h_prev  = (const float*)d_in[0];
    const float* dx      = (const float*)d_in[1];
    const float* Wa0     = (const float*)d_in[2];
    const float* ba0     = (const float*)d_in[3];
    const float* Wb0     = (const float*)d_in[4];
    const float* bb0     = (const float*)d_in[5];
    const float* Wa1     = (const float*)d_in[6];
    const float* ba1     = (const float*)d_in[7];
    const float* Wb1     = (const float*)d_in[8];
    const float* bb1     = (const float*)d_in[9];
    const float* W_alpha = (const float*)d_in[10];
    const float* b_alpha = (const float*)d_in[11];
    const float* W_beta  = (const float*)d_in[12];
    const float* b_beta  = (const float*)d_in[13];
    const float* W_gamma = (const float*)d_in[14];
    const float* b_gamma = (const float*)d_in[15];
    const float* W_c     = (const float*)d_in[16];
    const float* b_c     = (const float*)d_in[17];
    const float* W_out   = (const float*)d_in[18];
    float* out = (float*)d_out;

    int ntok = in_sizes[0] / 5;   // B*S
    int batches = ntok / SS;      // B

    scan_kernel<<<batches, 512>>>(dx);

    msc_hmma<<<GRID_MAIN, 128>>>(h_prev, dx,
                                 Wa0, ba0, Wb0, bb0, Wa1, ba1, Wb1, bb1,
                                 W_alpha, b_alpha, W_beta, b_beta,
                                 W_gamma, b_gamma, W_c, b_c, W_out,
                                 out, ntok);
}

// round 15
// speedup vs baseline: 2.3186x; 1.0180x over previous
#include <cuda_runtime.h>
#include <cuda_fp16.h>
#include <cstdint>

// ---------------------------------------------------------------------------
// MSC_Cell via warp-level HMMA (mma.sync m16n8k16 f16->f32), sm_103-safe.
//   128 tokens/tile, 4 warps x 32 tokens. Layer-to-layer data stays in
//   REGISTERS: the mma C-fragment layout equals the next mma's A-fragment
//   layout (per 16-k chunk), so gating repacks in-thread with no smem hop.
//   Only the initial row->fragment transpose and the 8-wide head outputs
//   touch shared memory inside the loop.
// ---------------------------------------------------------------------------

#define BB 128
#define SS 4096
#define NTILE ((BB * SS) / 128)
#define GRID_MAIN 444          // 3 CTAs/SM x 148 SMs, persistent
#define HS 24                  // halves per smem row (48B stride, LDSM conflict-free)

__device__ float g_temp[BB * SS];

// ---- helpers ----
__device__ __forceinline__ uint32_t smem_u32(const void* p) {
    uint32_t a;
    asm("{ .reg .u64 t; cvta.to.shared.u64 t, %1; cvt.u32.u64 %0, t; }"
        : "=r"(a) : "l"(p));
    return a;
}
__device__ __forceinline__ float tanh_ap(float x) {
    float y;
    asm("tanh.approx.f32 %0, %1;" : "=f"(y) : "f"(x));
    return y;
}
__device__ __forceinline__ uint32_t h2u(float a, float b) {
    __half2 h = __floats2half2_rn(a, b);
    return *reinterpret_cast<uint32_t*>(&h);
}
__device__ __forceinline__ void ldsm_x4(uint32_t* r, uint32_t addr) {
    asm volatile("ldmatrix.sync.aligned.m8n8.x4.shared.b16 {%0,%1,%2,%3}, [%4];"
                 : "=r"(r[0]), "=r"(r[1]), "=r"(r[2]), "=r"(r[3]) : "r"(addr));
}
__device__ __forceinline__ void ldsm_x2(uint32_t* r, uint32_t addr) {
    asm volatile("ldmatrix.sync.aligned.m8n8.x2.shared.b16 {%0,%1}, [%2];"
                 : "=r"(r[0]), "=r"(r[1]) : "r"(addr));
}
__device__ __forceinline__ void mma16816(float* c, const uint32_t* a,
                                         const uint32_t* b) {
    asm volatile(
        "mma.sync.aligned.m16n8k16.row.col.f32.f16.f16.f32 "
        "{%0,%1,%2,%3}, {%4,%5,%6,%7}, {%8,%9}, {%0,%1,%2,%3};"
        : "+f"(c[0]), "+f"(c[1]), "+f"(c[2]), "+f"(c[3])
        : "r"(a[0]), "r"(a[1]), "r"(a[2]), "r"(a[3]), "r"(b[0]), "r"(b[1]));
}

// ---------------------------------------------------------------------------
// Kernel 1: prefix scan (unchanged, proven).
// ---------------------------------------------------------------------------
__global__ void scan_kernel(const float* __restrict__ dx) {
    int b = blockIdx.x;
    const float* base = dx + (size_t)b * SS * 6;
    int t = threadIdx.x;  // 0..511

    float v[8];
    float run = 0.0f;
#pragma unroll
    for (int j = 0; j < 8; j++) {
        run += base[(t * 8 + j) * 6 + 2];
        v[j] = run;
    }
    float incl = run;
    int lane = t & 31, wid = t >> 5;
#pragma unroll
    for (int o = 1; o < 32; o <<= 1) {
        float n = __shfl_up_sync(0xffffffffu, incl, o);
        if (lane >= o) incl += n;
    }
    __shared__ float wsum[16];
    if (lane == 31) wsum[wid] = incl;
    __syncthreads();
    float woff = 0.0f;
    for (int k = 0; k < wid; k++) woff += wsum[k];
    float excl = woff + incl - run;
    float init = base[5];
    float* o = g_temp + (size_t)b * SS + t * 8;
#pragma unroll
    for (int j = 0; j < 8; j++) o[j] = excl + v[j] + init;
}

// ---------------------------------------------------------------------------
// Kernel 2: HMMA main, persistent. 128 threads = 4 warps x 32 tokens/tile.
// ---------------------------------------------------------------------------
__global__ __launch_bounds__(128) void msc_hmma(
    const float* __restrict__ h_prev, const float* __restrict__ dx,
    const float* __restrict__ Wa0, const float* __restrict__ ba0,
    const float* __restrict__ Wb0, const float* __restrict__ bb0,
    const float* __restrict__ Wa1, const float* __restrict__ ba1,
    const float* __restrict__ Wb1, const float* __restrict__ bb1,
    const float* __restrict__ W_alpha, const float* __restrict__ b_alpha,
    const float* __restrict__ W_beta,  const float* __restrict__ b_beta,
    const float* __restrict__ W_gamma, const float* __restrict__ b_gamma,
    const float* __restrict__ W_c,     const float* __restrict__ b_c,
    const float* __restrict__ W_out,
    float* __restrict__ out, int ntok) {
    __shared__ __align__(16) __half sIn[128 * HS];       // input rows (f16)
    __shared__ __align__(16) __half sW1[64 * HS];        // L0 weights, k 0..15
    __shared__ __align__(16) __half sW2[2][64 * HS];     // L1 weights, 2 k-chunks
    __shared__ __align__(16) __half sWh[2][8 * HS];      // head weights, 2 k-chunks
    __shared__ __align__(16) float sB0[64];
    __shared__ __align__(16) float sB1v[64];
    __shared__ __align__(16) float sBH[8];
    __shared__ __align__(16) float sWO[8];
    __shared__ __align__(16) float sHC[128 * 12];        // head C, stride 12 floats

    int tid = threadIdx.x;
    int lane = tid & 31;
    int wid = tid >> 5;

    // ---------------- one-time weight staging ----------------
    for (int i = tid; i < 64 * HS; i += 128) sW1[i] = __float2half(0.0f);
    __syncthreads();
    for (int idx = tid; idx < 64 * 9; idx += 128) {
        int n = idx / 9, k = idx % 9;
        float w = (n < 32) ? Wa0[k * 32 + n] : Wb0[k * 32 + (n - 32)];
        sW1[n * HS + k] = __float2half(w);
    }
    for (int idx = tid; idx < 64 * 32; idx += 128) {
        int n = idx / 32, k = idx % 32;
        float w = (n < 32) ? Wa1[k * 32 + n] : Wb1[k * 32 + (n - 32)];
        sW2[k >> 4][n * HS + (k & 15)] = __float2half(w);
    }
    for (int idx = tid; idx < 8 * 32; idx += 128) {
        int j = idx / 32, k = idx % 32;
        float w;
        if (j == 0)      w = W_alpha[k];
        else if (j == 1) w = W_beta[k];
        else if (j == 2) w = W_gamma[k];
        else             w = W_c[k * 5 + (j - 3)];
        sWh[k >> 4][j * HS + (k & 15)] = __float2half(w);
    }
    if (tid < 64) {
        sB0[tid]  = (tid < 32) ? ba0[tid] : bb0[tid - 32];
        sB1v[tid] = (tid < 32) ? ba1[tid] : bb1[tid - 32];
    }
    if (tid < 8) {
        float v;
        if (tid == 0)      v = b_alpha[0];
        else if (tid == 1) v = b_beta[0];
        else if (tid == 2) v = b_gamma[0];
        else               v = b_c[tid - 3];
        sBH[tid] = v;
        sWO[tid] = (tid < 5) ? W_out[tid] : 0.0f;
    }
    __syncthreads();

    uint32_t uIn = smem_u32(sIn);

    // ---------------- resident B fragments ----------------
    int bl = lane & 15;
    int brow = bl & 7;
    int bko = (bl >> 3) * 16;

    uint32_t w1f[8][2], w2f[2][8][2], whf[2][2];
    {
        uint32_t uW1 = smem_u32(sW1);
#pragma unroll
        for (int nt = 0; nt < 8; nt++)
            ldsm_x2(w1f[nt], uW1 + (nt * 8 + brow) * (HS * 2) + bko);
#pragma unroll
        for (int c = 0; c < 2; c++) {
            uint32_t uW2 = smem_u32(&sW2[c][0]);
#pragma unroll
            for (int nt = 0; nt < 8; nt++)
                ldsm_x2(w2f[c][nt], uW2 + (nt * 8 + brow) * (HS * 2) + bko);
        }
#pragma unroll
        for (int c = 0; c < 2; c++)
            ldsm_x2(whf[c], smem_u32(&sWh[c][0]) + brow * (HS * 2) + bko);
    }

    int ai = lane & 7;
    int asel = lane >> 3;
    int arow_off = (asel & 1) * 8 + ai;
    int abyte_off = (asel >> 1) * 16;

    int r0w = wid * 32;
    int lq = lane >> 2;
    int lr = lane & 3;

    // ---------------- persistent tile loop ----------------
    for (int tile = blockIdx.x; tile < NTILE; tile += GRID_MAIN) {
        int token = tile * 128 + r0w + lane;

        // ---- build input row (f16) ----
        {
            const float* hp = h_prev + (size_t)token * 5;
            const float* dp = dx + (size_t)token * 6;
            float d0 = dp[0], d1 = dp[1], d2 = dp[2];
            float temp = g_temp[token];
            float ssn = fmaf(d0, d0, fmaf(d1, d1, d2 * d2));
            float inv = __fdividef(1.0f, fmaxf(sqrtf(ssn), 1e-7f));
            __half* rowp = &sIn[(r0w + lane) * HS];
            uint4 b0 = make_uint4(h2u(hp[0], hp[1]), h2u(hp[2], hp[3]),
                                  h2u(hp[4], temp), h2u(d0 * inv, d1 * inv));
            uint4 b1 = make_uint4(h2u(d2 * inv, 0.0f), 0, 0, 0);
            *(uint4*)rowp = b0;
            *(uint4*)(rowp + 8) = b1;
        }
        __syncwarp();

        // ---- L0: bias init + K=16 mma ----
        float acc[2][8][4];
#pragma unroll
        for (int nt = 0; nt < 8; nt++) {
            float2 bv = *(const float2*)&sB0[nt * 8 + 2 * lr];
            acc[0][nt][0] = bv.x; acc[0][nt][1] = bv.y;
            acc[0][nt][2] = bv.x; acc[0][nt][3] = bv.y;
            acc[1][nt][0] = bv.x; acc[1][nt][1] = bv.y;
            acc[1][nt][2] = bv.x; acc[1][nt][3] = bv.y;
        }
#pragma unroll
        for (int m = 0; m < 2; m++) {
            uint32_t a[4];
            ldsm_x4(a, uIn + (r0w + m * 16 + arow_off) * (HS * 2) + abyte_off);
#pragma unroll
            for (int nt = 0; nt < 8; nt++) mma16816(acc[m][nt], a, w1f[nt]);
        }

        // ---- gate -> l1 A-fragments (pure registers) ----
        // C-frag (row lq cols 2lr,2lr+1; row lq+8 same) == A-frag layout:
        //   chunk c: a0=pack01(nt=2c) a1=pack23(nt=2c) a2=pack01(2c+1) a3=pack23(2c+1)
        uint32_t aF[2][2][4];
#pragma unroll
        for (int m = 0; m < 2; m++) {
#pragma unroll
            for (int nt = 0; nt < 4; nt++) {
                float g0 = tanh_ap(acc[m][nt][0]) * tanh_ap(acc[m][nt + 4][0]);
                float g1 = tanh_ap(acc[m][nt][1]) * tanh_ap(acc[m][nt + 4][1]);
                float g2 = tanh_ap(acc[m][nt][2]) * tanh_ap(acc[m][nt + 4][2]);
                float g3 = tanh_ap(acc[m][nt][3]) * tanh_ap(acc[m][nt + 4][3]);
                aF[m][nt >> 1][(nt & 1) * 2 + 0] = h2u(g0, g1);
                aF[m][nt >> 1][(nt & 1) * 2 + 1] = h2u(g2, g3);
            }
        }

        // ---- L1: bias init + K=32 (2 register chunks) ----
#pragma unroll
        for (int nt = 0; nt < 8; nt++) {
            float2 bv = *(const float2*)&sB1v[nt * 8 + 2 * lr];
            acc[0][nt][0] = bv.x; acc[0][nt][1] = bv.y;
            acc[0][nt][2] = bv.x; acc[0][nt][3] = bv.y;
            acc[1][nt][0] = bv.x; acc[1][nt][1] = bv.y;
            acc[1][nt][2] = bv.x; acc[1][nt][3] = bv.y;
        }
#pragma unroll
        for (int c = 0; c < 2; c++)
#pragma unroll
            for (int m = 0; m < 2; m++)
#pragma unroll
                for (int nt = 0; nt < 8; nt++)
                    mma16816(acc[m][nt], aF[m][c], w2f[c][nt]);

        // ---- gate -> l2 A-fragments ----
#pragma unroll
        for (int m = 0; m < 2; m++) {
#pragma unroll
            for (int nt = 0; nt < 4; nt++) {
                float g0 = tanh_ap(acc[m][nt][0]) * tanh_ap(acc[m][nt + 4][0]);
                float g1 = tanh_ap(acc[m][nt][1]) * tanh_ap(acc[m][nt + 4][1]);
                float g2 = tanh_ap(acc[m][nt][2]) * tanh_ap(acc[m][nt + 4][2]);
                float g3 = tanh_ap(acc[m][nt][3]) * tanh_ap(acc[m][nt + 4][3]);
                aF[m][nt >> 1][(nt & 1) * 2 + 0] = h2u(g0, g1);
                aF[m][nt >> 1][(nt & 1) * 2 + 1] = h2u(g2, g3);
            }
        }

        // ---- heads: K=32, N=8 ----
        float hacc[2][4];
        {
            float2 bv = *(const float2*)&sBH[2 * lr];
            hacc[0][0] = bv.x; hacc[0][1] = bv.y; hacc[0][2] = bv.x; hacc[0][3] = bv.y;
            hacc[1][0] = bv.x; hacc[1][1] = bv.y; hacc[1][2] = bv.x; hacc[1][3] = bv.y;
        }
#pragma unroll
        for (int c = 0; c < 2; c++)
#pragma unroll
            for (int m = 0; m < 2; m++)
                mma16816(hacc[m], aF[m][c], whf[c]);

#pragma unroll
        for (int m = 0; m < 2; m++) {
            int row = r0w + m * 16 + lq;
            *(float2*)&sHC[row * 12 + 2 * lr] = make_float2(hacc[m][0], hacc[m][1]);
            *(float2*)&sHC[(row + 8) * 12 + 2 * lr] = make_float2(hacc[m][2], hacc[m][3]);
        }
        __syncwarp();

        // ---- scalar epilogue (f32; h/d reloaded, L1-hot) ----
        {
            const float* hp = h_prev + (size_t)token * 5;
            const float* dp = dx + (size_t)token * 6;
            float h0 = hp[0], h1 = hp[1], h2 = hp[2], h3 = hp[3], h4 = hp[4];
            float d0 = dp[0], d1 = dp[1], d2 = dp[2];

            int tr = r0w + lane;
            float4 q0 = *(const float4*)&sHC[tr * 12];
            float4 q1 = *(const float4*)&sHC[tr * 12 + 4];
            float alpha = __expf(q0.x);
            float beta  = __expf(q0.y);
            float gamma = __expf(q0.z);
            float c0 = tanh_ap(q0.w), c1 = tanh_ap(q1.x), c2 = tanh_ap(q1.y);
            float c3 = tanh_ap(q1.z), c4 = tanh_ap(q1.w);

            float zarg = fmaf(alpha, fabsf(d0), fmaf(beta, d1, gamma * fabsf(d2)));
            float z = 1.0f - __expf(-zarg);

            float n0 = fmaf(z, c0 - h0, h0);
            float n1 = fmaf(z, c1 - h1, h1);
            float n2 = fmaf(z, c2 - h2, h2);
            float n3 = fmaf(z, c3 - h3, h3);
            float n4 = fmaf(z, c4 - h4, h4);

            float sigma = n0 * sWO[0];
            sigma = fmaf(n1, sWO[1], sigma);
            sigma = fmaf(n2, sWO[2], sigma);
            sigma = fmaf(n3, sWO[3], sigma);
            sigma = fmaf(n4, sWO[4], sigma);

            float* oh = out + (size_t)token * 5;
            oh[0] = n0; oh[1] = n1; oh[2] = n2; oh[3] = n3; oh[4] = n4;
            out[(size_t)ntok * 5 + token] = sigma;
        }
        __syncwarp();  // protect sIn / sHC before next-iter overwrite
    }
}

// ---------------------------------------------------------------------------
extern "C" void kernel_launch(void* const* d_in, const int* in_sizes, int n_in,
                              void* d_out, int out_size) {
    const float* h_prev  = (const float*)d_in[0];
    const float* dx      = (const float*)d_in[1];
    const float* Wa0     = (const float*)d_in[2];
    const float* ba0     = (const float*)d_in[3];
    const float* Wb0     = (const float*)d_in[4];
    const float* bb0     = (const float*)d_in[5];
    const float* Wa1     = (const float*)d_in[6];
    const float* ba1     = (const float*)d_in[7];
    const float* Wb1     = (const float*)d_in[8];
    const float* bb1     = (const float*)d_in[9];
    const float* W_alpha = (const float*)d_in[10];
    const float* b_alpha = (const float*)d_in[11];
    const float* W_beta  = (const float*)d_in[12];
    const float* b_beta  = (const float*)d_in[13];
    const float* W_gamma = (const float*)d_in[14];
    const float* b_gamma = (const float*)d_in[15];
    const float* W_c     = (const float*)d_in[16];
    const float* b_c     = (const float*)d_in[17];
    const float* W_out   = (const float*)d_in[18];
    float* out = (float*)d_out;

    int ntok = in_sizes[0] / 5;   // B*S
    int batches = ntok / SS;      // B

    scan_kernel<<<batches, 512>>>(dx);

    msc_hmma<<<GRID_MAIN, 128>>>(h_prev, dx,
                                 Wa0, ba0, Wb0, bb0, Wa1, ba1, Wb1, bb1,
                                 W_alpha, b_alpha, W_beta, b_beta,
                                 W_gamma, b_gamma, W_c, b_c, W_out,
                                 out, ntok);
}